// round 14
// baseline (speedup 1.0000x reference)
#include <cuda_runtime.h>
#include <cuda_fp16.h>
#include <math.h>
#include <stdint.h>

// Problem constants
#define B_      2
#define S_      2048
#define DM      2048
#define NQ_     16
#define NKV_    4
#define DH_     128
#define DR_     64
#define DKV_    512
#define DQC_    1536
#define BS_     (B_ * S_)        // 4096

// ---------------------------------------------------------------------------
// Scratch (device globals)
// ---------------------------------------------------------------------------
__device__ __align__(256) __half g_xh  [BS_ * DM];
__device__ __align__(256) __half g_krr [BS_ * (NKV_ * DR_)];
__device__ __align__(256) __half g_krh [BS_ * (NKV_ * DR_)];
__device__ __align__(256) __half g_ckvh[BS_ * DKV_];
__device__ __align__(256) __half g_kch [BS_ * (NKV_ * DH_)];
__device__ __align__(256) __half g_vh  [BS_ * (NKV_ * DH_)];
__device__ __align__(256) __half g_qch [BS_ * (NQ_ * DH_)];
__device__ __align__(256) __half g_qrh [BS_ * (NQ_ * DR_)];
__device__ __align__(256) __half g_attnh[BS_ * (NQ_ * DH_)];

// whx rows: [0,512) dkv | [512,768) kr | [768,2816) Wq | [2816,3840) qr
__device__ __align__(256) __half g_whx [3840 * DM];
__device__ __align__(256) __half g_whkv[1024 * DKV_];          // uk(/SIG) | uv
__device__ __align__(256) __half g_whuq[(NQ_ * DH_) * DQC_];
__device__ __align__(256) __half g_whdqh[DM * DQC_];
__device__ __align__(256) __half g_who [DM * (NQ_ * DH_)];

// ---------------------------------------------------------------------------
__device__ __forceinline__ uint32_t h2u(__half2 h) { return *(uint32_t*)&h; }

__device__ __forceinline__ void mma_fp16(float* d, const uint32_t* a,
                                         const uint32_t* b) {
    asm volatile(
        "mma.sync.aligned.m16n8k16.row.col.f32.f16.f16.f32 "
        "{%0,%1,%2,%3}, {%4,%5,%6,%7}, {%8,%9}, {%0,%1,%2,%3};"
        : "+f"(d[0]), "+f"(d[1]), "+f"(d[2]), "+f"(d[3])
        : "r"(a[0]), "r"(a[1]), "r"(a[2]), "r"(a[3]), "r"(b[0]), "r"(b[1]));
}

__device__ __forceinline__ void cp_async16(uint32_t saddr, const void* gptr) {
    asm volatile("cp.async.cg.shared.global [%0], [%1], 16;"
                 :: "r"(saddr), "l"(gptr));
}
#define CP_COMMIT() asm volatile("cp.async.commit_group;" ::: "memory")

__device__ __forceinline__ void ldmatrix_x4(uint32_t& d0, uint32_t& d1,
                                            uint32_t& d2, uint32_t& d3,
                                            uint32_t addr) {
    asm volatile("ldmatrix.sync.aligned.m8n8.x4.shared.b16 "
                 "{%0,%1,%2,%3}, [%4];"
                 : "=r"(d0), "=r"(d1), "=r"(d2), "=r"(d3) : "r"(addr));
}
__device__ __forceinline__ void ldmatrix_x4_trans(uint32_t& d0, uint32_t& d1,
                                                  uint32_t& d2, uint32_t& d3,
                                                  uint32_t addr) {
    asm volatile("ldmatrix.sync.aligned.m8n8.x4.trans.shared.b16 "
                 "{%0,%1,%2,%3}, [%4];"
                 : "=r"(d0), "=r"(d1), "=r"(d2), "=r"(d3) : "r"(addr));
}

extern __shared__ uint32_t dyn_smem_u32[];

// ---------------------------------------------------------------------------
__global__ __launch_bounds__(256)
void conv_half_kernel(const float* __restrict__ in, __half* __restrict__ out,
                      int n8) {
    int idx = blockIdx.x * blockDim.x + threadIdx.x;
    if (idx >= n8) return;
    float4 a = ((const float4*)in)[idx * 2];
    float4 b = ((const float4*)in)[idx * 2 + 1];
    uint4 o = { h2u(__floats2half2_rn(a.x, a.y)), h2u(__floats2half2_rn(a.z, a.w)),
                h2u(__floats2half2_rn(b.x, b.y)), h2u(__floats2half2_rn(b.z, b.w)) };
    ((uint4*)out)[idx] = o;
}

__global__ __launch_bounds__(256)
void transpose_h_kernel(const float* __restrict__ in, __half* __restrict__ out,
                        int K, int N, float mul) {
    __shared__ float t[32][33];
    int bx = blockIdx.x * 32;
    int by = blockIdx.y * 32;
    int x = bx + threadIdx.x;
#pragma unroll
    for (int i = threadIdx.y; i < 32; i += 8)
        t[i][threadIdx.x] = in[(size_t)(by + i) * N + x];
    __syncthreads();
    int xo = by + threadIdx.x;
#pragma unroll
    for (int i = threadIdx.y; i < 32; i += 8)
        out[(size_t)(bx + i) * K + xo] = __float2half(t[threadIdx.x][i] * mul);
}

// ---------------------------------------------------------------------------
// fp16 mma.sync GEMM, cp.async 4-stage ring, one barrier per K-tile,
// ldmatrix frags, multi-destination epilogue.
// ---------------------------------------------------------------------------
#define GLDH 36
#define GTILE (128 * GLDH)
#define GNST 4
#define GEMM_SMEM (GNST * 2 * GTILE * 4)     // 147456 B

template <int OM>
__global__ __launch_bounds__(256, 1)
void gemm_h(const __half* __restrict__ A, const __half* __restrict__ BT,
            void* d0v, void* d1v, void* d2v, void* d3v, float* mirror,
            int s1, int s2, int s3,
            int l0, int l1, int l2, int l3,
            int M, int K) {
    const uint32_t smem_base = (uint32_t)__cvta_generic_to_shared(dyn_smem_u32);
    const int tid = threadIdx.x;
    const int wid = tid >> 5, lane = tid & 31;
    const int g = lane >> 2, t = lane & 3;
    const int m0 = blockIdx.y * 128, n0 = blockIdx.x * 128;
    const int wm = (wid >> 2) * 64, wn = (wid & 3) * 32;
    const int grp = lane >> 3;
    const int l7 = lane & 7;

    float cf[4][4][4];
#pragma unroll
    for (int i = 0; i < 4; i++)
#pragma unroll
        for (int j = 0; j < 4; j++)
#pragma unroll
            for (int r = 0; r < 4; r++) cf[i][j][r] = 0.0f;

    const int T = K >> 6;

    auto stage = [&](int kt) {
        const int buf = kt % GNST;
        const int k0 = kt << 6;
        uint32_t aS = smem_base + buf * (2 * GTILE * 4);
        uint32_t bS = aS + GTILE * 4;
#pragma unroll
        for (int i = 0; i < 4; i++) {
            int idx = tid + (i << 8);
            int r = idx >> 3, c = idx & 7;
            uint32_t so = (uint32_t)(r * GLDH + c * 4) * 4;
            cp_async16(aS + so, A + (size_t)(m0 + r) * K + k0 + c * 8);
            cp_async16(bS + so, BT + (size_t)(n0 + r) * K + k0 + c * 8);
        }
        CP_COMMIT();
    };

    stage(0);
    if (T > 1) stage(1);
    if (T > 2) stage(2);

    for (int kt = 0; kt < T; kt++) {
        if (kt + 2 < T)      asm volatile("cp.async.wait_group 2;" ::: "memory");
        else if (kt + 1 < T) asm volatile("cp.async.wait_group 1;" ::: "memory");
        else                 asm volatile("cp.async.wait_group 0;" ::: "memory");
        __syncthreads();
        if (kt + 3 < T) stage(kt + 3);   // ring slot freed by this barrier

        const int buf = kt % GNST;
        const uint32_t aSa = smem_base + buf * (2 * GTILE * 4);
        const uint32_t bSa = aSa + GTILE * 4;
#pragma unroll
        for (int kc = 0; kc < 4; kc++) {
            const int acol = kc * 16 + ((grp >> 1) << 3);
            const int arow = ((grp & 1) << 3) + l7;
            uint32_t af[4][4], bf[4][2];
#pragma unroll
            for (int im = 0; im < 4; im++) {
                uint32_t addr = aSa + (uint32_t)((wm + im * 16 + arow) * 72 + acol) * 2;
                ldmatrix_x4(af[im][0], af[im][1], af[im][2], af[im][3], addr);
            }
            const int bcol = kc * 16 + ((grp & 1) << 3);
#pragma unroll
            for (int ip = 0; ip < 2; ip++) {
                int row = wn + (ip * 2 + (grp >> 1)) * 8 + l7;
                uint32_t addr = bSa + (uint32_t)(row * 72 + bcol) * 2;
                ldmatrix_x4(bf[ip * 2][0], bf[ip * 2][1],
                            bf[ip * 2 + 1][0], bf[ip * 2 + 1][1], addr);
            }
#pragma unroll
            for (int im = 0; im < 4; im++)
#pragma unroll
                for (int in_ = 0; in_ < 4; in_++)
                    mma_fp16(cf[im][in_], af[im], bf[in_]);
        }
    }

    void* dstv; int ld, cb, seg;
    if (n0 < s1)      { dstv = d0v; ld = l0; cb = n0;      seg = 0; }
    else if (n0 < s2) { dstv = d1v; ld = l1; cb = n0 - s1; seg = 1; }
    else if (n0 < s3) { dstv = d2v; ld = l2; cb = n0 - s2; seg = 2; }
    else              { dstv = d3v; ld = l3; cb = n0 - s3; seg = 3; }

#pragma unroll
    for (int im = 0; im < 4; im++) {
#pragma unroll
        for (int in_ = 0; in_ < 4; in_++) {
            int row = m0 + wm + im * 16 + g;
            int col = cb + wn + in_ * 8 + 2 * t;
            if (OM == 2) {
                float* dst = (float*)dstv;
                *(float2*)(dst + (size_t)row * ld + col) =
                    make_float2(cf[im][in_][0], cf[im][in_][1]);
                *(float2*)(dst + (size_t)(row + 8) * ld + col) =
                    make_float2(cf[im][in_][2], cf[im][in_][3]);
            } else {
                __half* dst = (__half*)dstv;
                *(uint32_t*)(dst + (size_t)row * ld + col) =
                    h2u(__floats2half2_rn(cf[im][in_][0], cf[im][in_][1]));
                *(uint32_t*)(dst + (size_t)(row + 8) * ld + col) =
                    h2u(__floats2half2_rn(cf[im][in_][2], cf[im][in_][3]));
                if (OM == 1 && seg == 0) {
                    *(float2*)(mirror + (size_t)row * ld + col) =
                        make_float2(cf[im][in_][0], cf[im][in_][1]);
                    *(float2*)(mirror + (size_t)(row + 8) * ld + col) =
                        make_float2(cf[im][in_][2], cf[im][in_][3]);
                }
            }
        }
    }
}

// ---------------------------------------------------------------------------
// RoPE for K (fp32 output + half copy)
// ---------------------------------------------------------------------------
__global__ __launch_bounds__(256)
void rope_k_kernel(const __half* __restrict__ kr_raw,
                   const float* __restrict__ cosc, const float* __restrict__ sinc,
                   float* __restrict__ kr_out, __half* __restrict__ kr_h) {
    int idx = blockIdx.x * blockDim.x + threadIdx.x;
    if (idx >= BS_ * NKV_ * 32) return;
    int d  = idx & 31;
    int kv = (idx >> 5) & 3;
    int bs = idx >> 7;
    int b = bs >> 11;
    int s = bs & 2047;
    int in_base = bs * (NKV_ * DR_) + kv * DR_;
    float x1 = __half2float(kr_raw[in_base + d]);
    float x2 = __half2float(kr_raw[in_base + d + 32]);
    float c = cosc[s * DR_ + d];
    float sn = sinc[s * DR_ + d];
    float y1 = x1 * c - x2 * sn;
    float y2 = x2 * c + x1 * sn;
    int ob = ((b * NKV_ + kv) * S_ + s) * DR_;
    kr_out[ob + d]      = y1;
    kr_out[ob + d + 32] = y2;
    kr_h[ob + d]        = __float2half(y1);
    kr_h[ob + d + 32]   = __float2half(y2);
}

// ---------------------------------------------------------------------------
// fp16 flash attention: 4-buffer K/V ring, one barrier/tile, register P,
// h2exp2 softmax.
// ---------------------------------------------------------------------------
#define AKP 200
#define AVP 136
#define AKW (64 * AKP)
#define AVW (64 * AVP)
#define ANST 4
#define AV0 (ANST * AKW)
#define ATTN_SMEM ((AV0 + ANST * AVW) * 2)   // 172032 B

__global__ __launch_bounds__(256, 1)
void attn_h_kernel(const __half* __restrict__ Qc, const __half* __restrict__ Qr,
                   const __half* __restrict__ Kc, const __half* __restrict__ Kr,
                   const __half* __restrict__ V,
                   const float* __restrict__ cosc, const float* __restrict__ sinc,
                   __half* __restrict__ Oattn) {
    __half* smh = (__half*)dyn_smem_u32;
    const uint32_t smem_base = (uint32_t)__cvta_generic_to_shared(smh);

    const int tid = threadIdx.x;
    const int w = tid >> 5, lane = tid & 31;
    const int g = lane >> 2, t = lane & 3;
    const int grp = lane >> 3;
    const int l7 = lane & 7;
    const int it = (gridDim.x - 1) - blockIdx.x;
    const int bh = blockIdx.y;
    const int b = bh >> 4, h = bh & 15;
    const int kvh = h >> 2;

    const int r0 = it * 128 + w * 16 + g;
    const int r1 = r0 + 8;

    const int srow = tid >> 2, sc = tid & 3;
    auto stageKV = [&](int jt) {
        const int buf = jt % ANST;
        const int kg = jt * 64 + srow;
        const __half* kcrow = Kc + (size_t)(b * S_ + kg) * (NKV_ * DH_) + kvh * DH_;
        const __half* krrow = Kr + ((size_t)(b * NKV_ + kvh) * S_ + kg) * DR_;
        const __half* vrow  = V  + (size_t)(b * S_ + kg) * (NKV_ * DH_) + kvh * DH_;
        uint32_t kS = smem_base + (buf * AKW + srow * AKP) * 2;
        uint32_t vS = smem_base + (AV0 + buf * AVW + srow * AVP) * 2;
#pragma unroll
        for (int j = 0; j < 6; j++) {
            int c = sc + j * 4;
            const __half* src = (c < 16) ? (kcrow + c * 8) : (krrow + (c - 16) * 8);
            cp_async16(kS + c * 16, src);
        }
#pragma unroll
        for (int j = 0; j < 4; j++) {
            int c = sc + j * 4;
            cp_async16(vS + c * 16, vrow + c * 8);
        }
        CP_COMMIT();
    };

    // Q fragments
    uint32_t qf[12][4];
    {
        const __half* qc0 = Qc + (size_t)(b * S_ + r0) * (NQ_ * DH_) + h * DH_;
        const __half* qc1 = Qc + (size_t)(b * S_ + r1) * (NQ_ * DH_) + h * DH_;
#pragma unroll
        for (int kc = 0; kc < 8; kc++) {
            int c = kc * 16 + 2 * t;
            qf[kc][0] = *(const uint32_t*)(qc0 + c);
            qf[kc][1] = *(const uint32_t*)(qc1 + c);
            qf[kc][2] = *(const uint32_t*)(qc0 + c + 8);
            qf[kc][3] = *(const uint32_t*)(qc1 + c + 8);
        }
        const __half* qr0 = Qr + (size_t)(b * S_ + r0) * (NQ_ * DR_) + h * DR_;
        const __half* qr1 = Qr + (size_t)(b * S_ + r1) * (NQ_ * DR_) + h * DR_;
#pragma unroll
        for (int p = 0; p < 2; p++) {
            int cA = p * 16 + 2 * t;
#pragma unroll
            for (int jj = 0; jj < 4; jj++) {
                const __half* qp = (jj & 1) ? qr1 : qr0;
                int s = (jj & 1) ? r1 : r0;
                int c = cA + (jj >> 1) * 8;
                float2 xA = __half22float2(*(const __half2*)(qp + c));
                float2 xB = __half22float2(*(const __half2*)(qp + c + 32));
                float2 cs = *(const float2*)(cosc + s * DR_ + c);
                float2 sn = *(const float2*)(sinc + s * DR_ + c);
                qf[8 + p][jj]  = h2u(__floats2half2_rn(
                    xA.x * cs.x - xB.x * sn.x, xA.y * cs.y - xB.y * sn.y));
                qf[10 + p][jj] = h2u(__floats2half2_rn(
                    xB.x * cs.x + xA.x * sn.x, xB.y * cs.y + xA.y * sn.y));
            }
        }
    }

    float oacc[16][4];
#pragma unroll
    for (int nt = 0; nt < 16; nt++)
#pragma unroll
        for (int r = 0; r < 4; r++) oacc[nt][r] = 0.0f;
    float m0 = -INFINITY, m1 = -INFINITY, l0 = 0.0f, l1 = 0.0f;

    const int jend = 2 * it + 2;
    stageKV(0);
    stageKV(1);
    if (jend > 2) stageKV(2);

    for (int jt = 0; jt < jend; jt++) {
        if (jt + 2 < jend)      asm volatile("cp.async.wait_group 2;" ::: "memory");
        else if (jt + 1 < jend) asm volatile("cp.async.wait_group 1;" ::: "memory");
        else                    asm volatile("cp.async.wait_group 0;" ::: "memory");
        __syncthreads();
        if (jt + 3 < jend) stageKV(jt + 3);

        const int buf = jt % ANST;
        const uint32_t kbase = smem_base + (buf * AKW) * 2;
        const uint32_t vbase = smem_base + (AV0 + buf * AVW) * 2;

        // --- S = Q @ K^T -----------------------------------------------
        float sacc[8][4];
#pragma unroll
        for (int nt = 0; nt < 8; nt++)
#pragma unroll
            for (int r = 0; r < 4; r++) sacc[nt][r] = 0.0f;
#pragma unroll
        for (int kc = 0; kc < 12; kc++) {
            const int bcol = kc * 16 + ((grp & 1) << 3);
            uint32_t bf[8][2];
#pragma unroll
            for (int ip = 0; ip < 4; ip++) {
                int row = (ip * 2 + (grp >> 1)) * 8 + l7;
                uint32_t addr = kbase + (uint32_t)(row * AKP + bcol) * 2;
                ldmatrix_x4(bf[ip * 2][0], bf[ip * 2][1],
                            bf[ip * 2 + 1][0], bf[ip * 2 + 1][1], addr);
            }
#pragma unroll
            for (int nt = 0; nt < 8; nt++)
                mma_fp16(sacc[nt], qf[kc], bf[nt]);
        }

        // --- mask + online softmax (log2 domain, half2 exp) -------------
        const bool masked = (jt >= 2 * it);
        float mx0 = -INFINITY, mx1 = -INFINITY;
#pragma unroll
        for (int nt = 0; nt < 8; nt++) {
            if (masked) {
                int c0 = jt * 64 + nt * 8 + 2 * t;
                int c1 = c0 + 1;
                if (c0 > r0) sacc[nt][0] = -INFINITY;
                if (c1 > r0) sacc[nt][1] = -INFINITY;
                if (c0 > r1) sacc[nt][2] = -INFINITY;
                if (c1 > r1) sacc[nt][3] = -INFINITY;
            }
            mx0 = fmaxf(mx0, fmaxf(sacc[nt][0], sacc[nt][1]));
            mx1 = fmaxf(mx1, fmaxf(sacc[nt][2], sacc[nt][3]));
        }
        mx0 = fmaxf(mx0, __shfl_xor_sync(0xffffffffu, mx0, 1));
        mx0 = fmaxf(mx0, __shfl_xor_sync(0xffffffffu, mx0, 2));
        mx1 = fmaxf(mx1, __shfl_xor_sync(0xffffffffu, mx1, 1));
        mx1 = fmaxf(mx1, __shfl_xor_sync(0xffffffffu, mx1, 2));

        float mn0 = fmaxf(m0, mx0), mn1 = fmaxf(m1, mx1);
        float corr0 = exp2f(m0 - mn0), corr1 = exp2f(m1 - mn1);
        m0 = mn0; m1 = mn1;
        float ps0 = 0.0f, ps1 = 0.0f;
        uint32_t pf[8][2];
#pragma unroll
        for (int nt = 0; nt < 8; nt++) {
            __half2 pa = h2exp2(__floats2half2_rn(sacc[nt][0] - mn0,
                                                  sacc[nt][1] - mn0));
            __half2 pb = h2exp2(__floats2half2_rn(sacc[nt][2] - mn1,
                                                  sacc[nt][3] - mn1));
            pf[nt][0] = h2u(pa);
            pf[nt][1] = h2u(pb);
            float2 fa = __half22float2(pa), fb = __half22float2(pb);
            ps0 += fa.x + fa.y;
            ps1 += fb.x + fb.y;
        }
        ps0 += __shfl_xor_sync(0xffffffffu, ps0, 1);
        ps0 += __shfl_xor_sync(0xffffffffu, ps0, 2);
        ps1 += __shfl_xor_sync(0xffffffffu, ps1, 1);
        ps1 += __shfl_xor_sync(0xffffffffu, ps1, 2);
        l0 = l0 * corr0 + ps0;
        l1 = l1 * corr1 + ps1;
#pragma unroll
        for (int nt = 0; nt < 16; nt++) {
            oacc[nt][0] *= corr0; oacc[nt][1] *= corr0;
            oacc[nt][2] *= corr1; oacc[nt][3] *= corr1;
        }

        // --- O += P @ V ------------------------------------------------
#pragma unroll
        for (int kc = 0; kc < 4; kc++) {
            uint32_t af[4] = { pf[2 * kc][0], pf[2 * kc][1],
                               pf[2 * kc + 1][0], pf[2 * kc + 1][1] };
            int vrow = kc * 16 + (lane & 15);
            int vhi  = (lane >> 4) & 1;
#pragma unroll
            for (int np = 0; np < 8; np++) {
                uint32_t addr = vbase + (uint32_t)(vrow * AVP + np * 16 + vhi * 8) * 2;
                uint32_t b0, b1, b2, b3;
                ldmatrix_x4_trans(b0, b1, b2, b3, addr);
                uint32_t bb0[2] = { b0, b1 }, bb1[2] = { b2, b3 };
                mma_fp16(oacc[np * 2],     af, bb0);
                mma_fp16(oacc[np * 2 + 1], af, bb1);
            }
        }
    }

    float il0 = 1.0f / l0, il1 = 1.0f / l1;
#pragma unroll
    for (int nt = 0; nt < 16; nt++) {
        int col = nt * 8 + 2 * t;
        *(uint32_t*)(Oattn + (size_t)(b * S_ + r0) * (NQ_ * DH_) + h * DH_ + col) =
            h2u(__floats2half2_rn(oacc[nt][0] * il0, oacc[nt][1] * il0));
        *(uint32_t*)(Oattn + (size_t)(b * S_ + r1) * (NQ_ * DH_) + h * DH_ + col) =
            h2u(__floats2half2_rn(oacc[nt][2] * il1, oacc[nt][3] * il1));
    }
}

// ---------------------------------------------------------------------------
extern "C" void kernel_launch(void* const* d_in, const int* in_sizes, int n_in,
                              void* d_out, int out_size) {
    const float* x     = (const float*)d_in[0];
    const float* cosc  = (const float*)d_in[1];
    const float* sinc  = (const float*)d_in[2];
    const float* W_DKV = (const float*)d_in[5];
    const float* W_UK  = (const float*)d_in[6];
    const float* W_UV  = (const float*)d_in[7];
    const float* W_DQ  = (const float*)d_in[8];
    const float* W_UQ  = (const float*)d_in[9];
    const float* W_KR  = (const float*)d_in[10];
    const float* W_QR  = (const float*)d_in[11];
    const float* W_O   = (const float*)d_in[12];

    float* out    = (float*)d_out;
    float* c_kv   = out + B_ * S_ * DM;
    float* k_rope = c_kv + B_ * S_ * DKV_;

    __half *xh, *krr, *krh, *ckvh, *kch, *vh, *qch, *qrh, *attnh;
    __half *whx, *whkv, *whuq, *whdqh, *who;
    cudaGetSymbolAddress((void**)&xh,    g_xh);
    cudaGetSymbolAddress((void**)&krr,   g_krr);
    cudaGetSymbolAddress((void**)&krh,   g_krh);
    cudaGetSymbolAddress((void**)&ckvh,  g_ckvh);
    cudaGetSymbolAddress((void**)&kch,   g_kch);
    cudaGetSymbolAddress((void**)&vh,    g_vh);
    cudaGetSymbolAddress((void**)&qch,   g_qch);
    cudaGetSymbolAddress((void**)&qrh,   g_qrh);
    cudaGetSymbolAddress((void**)&attnh, g_attnh);
    cudaGetSymbolAddress((void**)&whx,   g_whx);
    cudaGetSymbolAddress((void**)&whkv,  g_whkv);
    cudaGetSymbolAddress((void**)&whuq,  g_whuq);
    cudaGetSymbolAddress((void**)&whdqh, g_whdqh);
    cudaGetSymbolAddress((void**)&who,   g_who);

    cudaFuncSetAttribute(attn_h_kernel, cudaFuncAttributeMaxDynamicSharedMemorySize,
                         ATTN_SMEM);
    cudaFuncSetAttribute(gemm_h<0>, cudaFuncAttributeMaxDynamicSharedMemorySize,
                         GEMM_SMEM);
    cudaFuncSetAttribute(gemm_h<1>, cudaFuncAttributeMaxDynamicSharedMemorySize,
                         GEMM_SMEM);
    cudaFuncSetAttribute(gemm_h<2>, cudaFuncAttributeMaxDynamicSharedMemorySize,
                         GEMM_SMEM);

    // Handles created once and cached (correctness call precedes the
    // pre-capture memory baseline; capture/replay calls allocate nothing).
    static cudaStream_t s1 = nullptr, s2 = nullptr;
    static cudaEvent_t eFork, eConv, eQc, eG1, eRk, eKV;
    if (!s1) {
        cudaStreamCreateWithFlags(&s1, cudaStreamNonBlocking);
        cudaStreamCreateWithFlags(&s2, cudaStreamNonBlocking);
        cudaEventCreateWithFlags(&eFork, cudaEventDisableTiming);
        cudaEventCreateWithFlags(&eConv, cudaEventDisableTiming);
        cudaEventCreateWithFlags(&eQc,   cudaEventDisableTiming);
        cudaEventCreateWithFlags(&eG1,   cudaEventDisableTiming);
        cudaEventCreateWithFlags(&eRk,   cudaEventDisableTiming);
        cudaEventCreateWithFlags(&eKV,   cudaEventDisableTiming);
    }

    cudaEventRecord(eFork, 0);
    cudaStreamWaitEvent(s1, eFork, 0);
    cudaStreamWaitEvent(s2, eFork, 0);

    const float scale2 = 0.072168783648703220563f * 1.4426950408889634f;
    const float SIG = 512.0f;
    dim3 tb(32, 8);
    const int BIG = 1 << 30;

    // s1: Wq combine chain (overlaps GEMM1 on main)
    conv_half_kernel<<<(DM * DQC_ / 8 + 255) / 256, 256, 0, s1>>>(W_DQ, whdqh, DM * DQC_ / 8);
    transpose_h_kernel<<<dim3((NQ_ * DH_) / 32, DQC_ / 32), tb, 0, s1>>>(W_UQ, whuq, DQC_, NQ_ * DH_, scale2 * SIG);
    gemm_h<0><<<dim3(DM / 128, (NQ_ * DH_) / 128), 256, GEMM_SMEM, s1>>>(
        whuq, whdqh, whx + 768 * DM, whx + 768 * DM, whx + 768 * DM, whx + 768 * DM,
        nullptr, BIG, BIG, BIG, DM, DM, DM, DM, NQ_ * DH_, DQC_);
    cudaEventRecord(eQc, s1);

    // s2: x -> half, then uk/uv/o transposes
    conv_half_kernel<<<(BS_ * DM / 8 + 255) / 256, 256, 0, s2>>>(x, xh, BS_ * DM / 8);
    cudaEventRecord(eConv, s2);
    transpose_h_kernel<<<dim3((NKV_ * DH_) / 32, DKV_ / 32), tb, 0, s2>>>(W_UK, whkv, DKV_, NKV_ * DH_, 1.0f / SIG);
    transpose_h_kernel<<<dim3((NKV_ * DH_) / 32, DKV_ / 32), tb, 0, s2>>>(W_UV, whkv + 512 * DKV_, DKV_, NKV_ * DH_, 1.0f);
    transpose_h_kernel<<<dim3(DM / 32, (NQ_ * DH_) / 32), tb, 0, s2>>>(W_O, who, NQ_ * DH_, DM, 1.0f);

    // main: dkv/kr/qr transposes, then GEMM1 [c_kv | kr]  (no Wq dependency)
    transpose_h_kernel<<<dim3(DKV_ / 32, DM / 32), tb>>>(W_DKV, whx, DM, DKV_, 1.0f);
    transpose_h_kernel<<<dim3((NKV_ * DR_) / 32, DM / 32), tb>>>(W_KR, whx + 512 * DM, DM, NKV_ * DR_, 1.0f);
    transpose_h_kernel<<<dim3((NQ_ * DR_) / 32, DM / 32), tb>>>(W_QR, whx + 2816 * DM, DM, NQ_ * DR_, scale2);
    cudaStreamWaitEvent(0, eConv, 0);
    gemm_h<1><<<dim3(768 / 128, BS_ / 128), 256, GEMM_SMEM>>>(
        xh, whx, ckvh, krr, krr, krr, c_kv, 512, BIG, BIG,
        DKV_, NKV_ * DR_, NKV_ * DR_, NKV_ * DR_, BS_, DM);
    cudaEventRecord(eG1, 0);

    // main: GEMM2 [Qc | qr]  (needs Wq combine)
    cudaStreamWaitEvent(0, eQc, 0);
    gemm_h<0><<<dim3(3072 / 128, BS_ / 128), 256, GEMM_SMEM>>>(
        xh, whx + 768 * DM, qch, qrh, qrh, qrh, nullptr, 2048, BIG, BIG,
        NQ_ * DH_, NQ_ * DR_, NQ_ * DR_, NQ_ * DR_, BS_, DM);

    // s1: rope_k concurrent with GEMM2
    cudaStreamWaitEvent(s1, eG1, 0);
    rope_k_kernel<<<(BS_ * NKV_ * 32 + 255) / 256, 256, 0, s1>>>(krr, cosc, sinc, k_rope, krh);
    cudaEventRecord(eRk, s1);

    // s2: kv-GEMM concurrent with GEMM2 (uk/uv transposes in-stream earlier)
    cudaStreamWaitEvent(s2, eG1, 0);
    gemm_h<0><<<dim3(1024 / 128, BS_ / 128), 256, GEMM_SMEM, s2>>>(
        ckvh, whkv, kch, vh, vh, vh, nullptr, 512, BIG, BIG,
        NKV_ * DH_, NKV_ * DH_, NKV_ * DH_, NKV_ * DH_, BS_, DKV_);
    cudaEventRecord(eKV, s2);

    // main: join, attention, output GEMM
    cudaStreamWaitEvent(0, eRk, 0);
    cudaStreamWaitEvent(0, eKV, 0);
    attn_h_kernel<<<dim3(S_ / 128, B_ * NQ_), 256, ATTN_SMEM>>>(
        qch, qrh, kch, krh, vh, cosc, sinc, attnh);
    gemm_h<2><<<dim3(DM / 128, BS_ / 128), 256, GEMM_SMEM>>>(
        attnh, who, out, out, out, out, nullptr, BIG, BIG, BIG,
        DM, DM, DM, DM, BS_, NQ_ * DH_);
}

// round 15
// speedup vs baseline: 1.1074x; 1.1074x over previous
#include <cuda_runtime.h>
#include <cuda_fp16.h>
#include <math.h>
#include <stdint.h>

// Problem constants
#define B_      2
#define S_      2048
#define DM      2048
#define NQ_     16
#define NKV_    4
#define DH_     128
#define DR_     64
#define DKV_    512
#define DQC_    1536
#define BS_     (B_ * S_)        // 4096

// ---------------------------------------------------------------------------
// Scratch (device globals)
// ---------------------------------------------------------------------------
__device__ __align__(256) __half g_xh  [BS_ * DM];
__device__ __align__(256) __half g_krr [BS_ * (NKV_ * DR_)];
__device__ __align__(256) __half g_krh [BS_ * (NKV_ * DR_)];
__device__ __align__(256) __half g_ckvh[BS_ * DKV_];
__device__ __align__(256) __half g_kch [BS_ * (NKV_ * DH_)];
__device__ __align__(256) __half g_vh  [BS_ * (NKV_ * DH_)];
__device__ __align__(256) __half g_qch [BS_ * (NQ_ * DH_)];
__device__ __align__(256) __half g_qrh [BS_ * (NQ_ * DR_)];
__device__ __align__(256) __half g_attnh[BS_ * (NQ_ * DH_)];

// whx rows: [0,512) dkv | [512,768) kr | [768,2816) Wq | [2816,3840) qr
__device__ __align__(256) __half g_whx [3840 * DM];
__device__ __align__(256) __half g_whkv[1024 * DKV_];          // uk(/SIG) | uv
__device__ __align__(256) __half g_whuq[(NQ_ * DH_) * DQC_];
__device__ __align__(256) __half g_whdqh[DM * DQC_];
__device__ __align__(256) __half g_who [DM * (NQ_ * DH_)];

// ---------------------------------------------------------------------------
__device__ __forceinline__ uint32_t h2u(__half2 h) { return *(uint32_t*)&h; }

__device__ __forceinline__ void mma_fp16(float* d, const uint32_t* a,
                                         const uint32_t* b) {
    asm volatile(
        "mma.sync.aligned.m16n8k16.row.col.f32.f16.f16.f32 "
        "{%0,%1,%2,%3}, {%4,%5,%6,%7}, {%8,%9}, {%0,%1,%2,%3};"
        : "+f"(d[0]), "+f"(d[1]), "+f"(d[2]), "+f"(d[3])
        : "r"(a[0]), "r"(a[1]), "r"(a[2]), "r"(a[3]), "r"(b[0]), "r"(b[1]));
}

__device__ __forceinline__ void cp_async16(uint32_t saddr, const void* gptr) {
    asm volatile("cp.async.cg.shared.global [%0], [%1], 16;"
                 :: "r"(saddr), "l"(gptr));
}
#define CP_COMMIT() asm volatile("cp.async.commit_group;" ::: "memory")

__device__ __forceinline__ void ldmatrix_x4(uint32_t& d0, uint32_t& d1,
                                            uint32_t& d2, uint32_t& d3,
                                            uint32_t addr) {
    asm volatile("ldmatrix.sync.aligned.m8n8.x4.shared.b16 "
                 "{%0,%1,%2,%3}, [%4];"
                 : "=r"(d0), "=r"(d1), "=r"(d2), "=r"(d3) : "r"(addr));
}
__device__ __forceinline__ void ldmatrix_x4_trans(uint32_t& d0, uint32_t& d1,
                                                  uint32_t& d2, uint32_t& d3,
                                                  uint32_t addr) {
    asm volatile("ldmatrix.sync.aligned.m8n8.x4.trans.shared.b16 "
                 "{%0,%1,%2,%3}, [%4];"
                 : "=r"(d0), "=r"(d1), "=r"(d2), "=r"(d3) : "r"(addr));
}

extern __shared__ uint32_t dyn_smem_u32[];

// ---------------------------------------------------------------------------
__global__ __launch_bounds__(256)
void conv_half_kernel(const float* __restrict__ in, __half* __restrict__ out,
                      int n8) {
    int idx = blockIdx.x * blockDim.x + threadIdx.x;
    if (idx >= n8) return;
    float4 a = ((const float4*)in)[idx * 2];
    float4 b = ((const float4*)in)[idx * 2 + 1];
    uint4 o = { h2u(__floats2half2_rn(a.x, a.y)), h2u(__floats2half2_rn(a.z, a.w)),
                h2u(__floats2half2_rn(b.x, b.y)), h2u(__floats2half2_rn(b.z, b.w)) };
    ((uint4*)out)[idx] = o;
}

__global__ __launch_bounds__(256)
void transpose_h_kernel(const float* __restrict__ in, __half* __restrict__ out,
                        int K, int N, float mul) {
    __shared__ float t[32][33];
    int bx = blockIdx.x * 32;
    int by = blockIdx.y * 32;
    int x = bx + threadIdx.x;
#pragma unroll
    for (int i = threadIdx.y; i < 32; i += 8)
        t[i][threadIdx.x] = in[(size_t)(by + i) * N + x];
    __syncthreads();
    int xo = by + threadIdx.x;
#pragma unroll
    for (int i = threadIdx.y; i < 32; i += 8)
        out[(size_t)(bx + i) * K + xo] = __float2half(t[threadIdx.x][i] * mul);
}

// ---------------------------------------------------------------------------
// fp16 mma.sync GEMM, cp.async 3-stage ring, one barrier per K-tile,
// ldmatrix frags, multi-destination epilogue.
// ---------------------------------------------------------------------------
#define GLDH 36
#define GTILE (128 * GLDH)
#define GNST 3
#define GEMM_SMEM (GNST * 2 * GTILE * 4)

template <int OM>
__global__ __launch_bounds__(256, 1)
void gemm_h(const __half* __restrict__ A, const __half* __restrict__ BT,
            void* d0v, void* d1v, void* d2v, void* d3v, float* mirror,
            int s1, int s2, int s3,
            int l0, int l1, int l2, int l3,
            int M, int K) {
    const uint32_t smem_base = (uint32_t)__cvta_generic_to_shared(dyn_smem_u32);
    const int tid = threadIdx.x;
    const int wid = tid >> 5, lane = tid & 31;
    const int g = lane >> 2, t = lane & 3;
    const int m0 = blockIdx.y * 128, n0 = blockIdx.x * 128;
    const int wm = (wid >> 2) * 64, wn = (wid & 3) * 32;
    const int grp = lane >> 3;
    const int l7 = lane & 7;

    float cf[4][4][4];
#pragma unroll
    for (int i = 0; i < 4; i++)
#pragma unroll
        for (int j = 0; j < 4; j++)
#pragma unroll
            for (int r = 0; r < 4; r++) cf[i][j][r] = 0.0f;

    const int T = K >> 6;

    auto stage = [&](int kt) {
        const int buf = kt % GNST;
        const int k0 = kt << 6;
        uint32_t aS = smem_base + buf * (2 * GTILE * 4);
        uint32_t bS = aS + GTILE * 4;
#pragma unroll
        for (int i = 0; i < 4; i++) {
            int idx = tid + (i << 8);
            int r = idx >> 3, c = idx & 7;
            uint32_t so = (uint32_t)(r * GLDH + c * 4) * 4;
            cp_async16(aS + so, A + (size_t)(m0 + r) * K + k0 + c * 8);
            cp_async16(bS + so, BT + (size_t)(n0 + r) * K + k0 + c * 8);
        }
        CP_COMMIT();
    };

    stage(0);
    stage(1);

    for (int kt = 0; kt < T; kt++) {
        if (kt + 1 < T) asm volatile("cp.async.wait_group 1;" ::: "memory");
        else            asm volatile("cp.async.wait_group 0;" ::: "memory");
        __syncthreads();
        if (kt + 2 < T) stage(kt + 2);

        const int buf = kt % GNST;
        const uint32_t aSa = smem_base + buf * (2 * GTILE * 4);
        const uint32_t bSa = aSa + GTILE * 4;
#pragma unroll
        for (int kc = 0; kc < 4; kc++) {
            const int acol = kc * 16 + ((grp >> 1) << 3);
            const int arow = ((grp & 1) << 3) + l7;
            uint32_t af[4][4], bf[4][2];
#pragma unroll
            for (int im = 0; im < 4; im++) {
                uint32_t addr = aSa + (uint32_t)((wm + im * 16 + arow) * 72 + acol) * 2;
                ldmatrix_x4(af[im][0], af[im][1], af[im][2], af[im][3], addr);
            }
            const int bcol = kc * 16 + ((grp & 1) << 3);
#pragma unroll
            for (int ip = 0; ip < 2; ip++) {
                int row = wn + (ip * 2 + (grp >> 1)) * 8 + l7;
                uint32_t addr = bSa + (uint32_t)(row * 72 + bcol) * 2;
                ldmatrix_x4(bf[ip * 2][0], bf[ip * 2][1],
                            bf[ip * 2 + 1][0], bf[ip * 2 + 1][1], addr);
            }
#pragma unroll
            for (int im = 0; im < 4; im++)
#pragma unroll
                for (int in_ = 0; in_ < 4; in_++)
                    mma_fp16(cf[im][in_], af[im], bf[in_]);
        }
    }

    void* dstv; int ld, cb, seg;
    if (n0 < s1)      { dstv = d0v; ld = l0; cb = n0;      seg = 0; }
    else if (n0 < s2) { dstv = d1v; ld = l1; cb = n0 - s1; seg = 1; }
    else if (n0 < s3) { dstv = d2v; ld = l2; cb = n0 - s2; seg = 2; }
    else              { dstv = d3v; ld = l3; cb = n0 - s3; seg = 3; }

#pragma unroll
    for (int im = 0; im < 4; im++) {
#pragma unroll
        for (int in_ = 0; in_ < 4; in_++) {
            int row = m0 + wm + im * 16 + g;
            int col = cb + wn + in_ * 8 + 2 * t;
            if (OM == 2) {
                float* dst = (float*)dstv;
                *(float2*)(dst + (size_t)row * ld + col) =
                    make_float2(cf[im][in_][0], cf[im][in_][1]);
                *(float2*)(dst + (size_t)(row + 8) * ld + col) =
                    make_float2(cf[im][in_][2], cf[im][in_][3]);
            } else {
                __half* dst = (__half*)dstv;
                *(uint32_t*)(dst + (size_t)row * ld + col) =
                    h2u(__floats2half2_rn(cf[im][in_][0], cf[im][in_][1]));
                *(uint32_t*)(dst + (size_t)(row + 8) * ld + col) =
                    h2u(__floats2half2_rn(cf[im][in_][2], cf[im][in_][3]));
                if (OM == 1 && seg == 0) {
                    *(float2*)(mirror + (size_t)row * ld + col) =
                        make_float2(cf[im][in_][0], cf[im][in_][1]);
                    *(float2*)(mirror + (size_t)(row + 8) * ld + col) =
                        make_float2(cf[im][in_][2], cf[im][in_][3]);
                }
            }
        }
    }
}

// ---------------------------------------------------------------------------
// RoPE for K (fp32 output + half copy)
// ---------------------------------------------------------------------------
__global__ __launch_bounds__(256)
void rope_k_kernel(const __half* __restrict__ kr_raw,
                   const float* __restrict__ cosc, const float* __restrict__ sinc,
                   float* __restrict__ kr_out, __half* __restrict__ kr_h) {
    int idx = blockIdx.x * blockDim.x + threadIdx.x;
    if (idx >= BS_ * NKV_ * 32) return;
    int d  = idx & 31;
    int kv = (idx >> 5) & 3;
    int bs = idx >> 7;
    int b = bs >> 11;
    int s = bs & 2047;
    int in_base = bs * (NKV_ * DR_) + kv * DR_;
    float x1 = __half2float(kr_raw[in_base + d]);
    float x2 = __half2float(kr_raw[in_base + d + 32]);
    float c = cosc[s * DR_ + d];
    float sn = sinc[s * DR_ + d];
    float y1 = x1 * c - x2 * sn;
    float y2 = x2 * c + x1 * sn;
    int ob = ((b * NKV_ + kv) * S_ + s) * DR_;
    kr_out[ob + d]      = y1;
    kr_out[ob + d + 32] = y2;
    kr_h[ob + d]        = __float2half(y1);
    kr_h[ob + d + 32]   = __float2half(y2);
}

// ---------------------------------------------------------------------------
// fp16 flash attention: 3-buffer K/V ring, one barrier/tile, register P,
// h2exp2 softmax. bh_base selects the batch half (tail-overlap with W_O).
// ---------------------------------------------------------------------------
#define AKP 200
#define AVP 136
#define AKW (64 * AKP)
#define AVW (64 * AVP)
#define AV0 (3 * AKW)
#define ATTN_SMEM ((AV0 + 3 * AVW) * 2)    // 129024 B

__global__ __launch_bounds__(256, 1)
void attn_h_kernel(const __half* __restrict__ Qc, const __half* __restrict__ Qr,
                   const __half* __restrict__ Kc, const __half* __restrict__ Kr,
                   const __half* __restrict__ V,
                   const float* __restrict__ cosc, const float* __restrict__ sinc,
                   __half* __restrict__ Oattn, int bh_base) {
    __half* smh = (__half*)dyn_smem_u32;
    const uint32_t smem_base = (uint32_t)__cvta_generic_to_shared(smh);

    const int tid = threadIdx.x;
    const int w = tid >> 5, lane = tid & 31;
    const int g = lane >> 2, t = lane & 3;
    const int grp = lane >> 3;
    const int l7 = lane & 7;
    const int it = (gridDim.x - 1) - blockIdx.x;
    const int bh = blockIdx.y + bh_base;
    const int b = bh >> 4, h = bh & 15;
    const int kvh = h >> 2;

    const int r0 = it * 128 + w * 16 + g;
    const int r1 = r0 + 8;

    const int srow = tid >> 2, sc = tid & 3;
    auto stageKV = [&](int jt) {
        const int buf = jt % 3;
        const int kg = jt * 64 + srow;
        const __half* kcrow = Kc + (size_t)(b * S_ + kg) * (NKV_ * DH_) + kvh * DH_;
        const __half* krrow = Kr + ((size_t)(b * NKV_ + kvh) * S_ + kg) * DR_;
        const __half* vrow  = V  + (size_t)(b * S_ + kg) * (NKV_ * DH_) + kvh * DH_;
        uint32_t kS = smem_base + (buf * AKW + srow * AKP) * 2;
        uint32_t vS = smem_base + (AV0 + buf * AVW + srow * AVP) * 2;
#pragma unroll
        for (int j = 0; j < 6; j++) {
            int c = sc + j * 4;
            const __half* src = (c < 16) ? (kcrow + c * 8) : (krrow + (c - 16) * 8);
            cp_async16(kS + c * 16, src);
        }
#pragma unroll
        for (int j = 0; j < 4; j++) {
            int c = sc + j * 4;
            cp_async16(vS + c * 16, vrow + c * 8);
        }
        CP_COMMIT();
    };

    // Q fragments
    uint32_t qf[12][4];
    {
        const __half* qc0 = Qc + (size_t)(b * S_ + r0) * (NQ_ * DH_) + h * DH_;
        const __half* qc1 = Qc + (size_t)(b * S_ + r1) * (NQ_ * DH_) + h * DH_;
#pragma unroll
        for (int kc = 0; kc < 8; kc++) {
            int c = kc * 16 + 2 * t;
            qf[kc][0] = *(const uint32_t*)(qc0 + c);
            qf[kc][1] = *(const uint32_t*)(qc1 + c);
            qf[kc][2] = *(const uint32_t*)(qc0 + c + 8);
            qf[kc][3] = *(const uint32_t*)(qc1 + c + 8);
        }
        const __half* qr0 = Qr + (size_t)(b * S_ + r0) * (NQ_ * DR_) + h * DR_;
        const __half* qr1 = Qr + (size_t)(b * S_ + r1) * (NQ_ * DR_) + h * DR_;
#pragma unroll
        for (int p = 0; p < 2; p++) {
            int cA = p * 16 + 2 * t;
#pragma unroll
            for (int jj = 0; jj < 4; jj++) {
                const __half* qp = (jj & 1) ? qr1 : qr0;
                int s = (jj & 1) ? r1 : r0;
                int c = cA + (jj >> 1) * 8;
                float2 xA = __half22float2(*(const __half2*)(qp + c));
                float2 xB = __half22float2(*(const __half2*)(qp + c + 32));
                float2 cs = *(const float2*)(cosc + s * DR_ + c);
                float2 sn = *(const float2*)(sinc + s * DR_ + c);
                qf[8 + p][jj]  = h2u(__floats2half2_rn(
                    xA.x * cs.x - xB.x * sn.x, xA.y * cs.y - xB.y * sn.y));
                qf[10 + p][jj] = h2u(__floats2half2_rn(
                    xB.x * cs.x + xA.x * sn.x, xB.y * cs.y + xA.y * sn.y));
            }
        }
    }

    float oacc[16][4];
#pragma unroll
    for (int nt = 0; nt < 16; nt++)
#pragma unroll
        for (int r = 0; r < 4; r++) oacc[nt][r] = 0.0f;
    float m0 = -INFINITY, m1 = -INFINITY, l0 = 0.0f, l1 = 0.0f;

    const int jend = 2 * it + 2;
    stageKV(0);
    stageKV(1);

    for (int jt = 0; jt < jend; jt++) {
        if (jt + 1 < jend) asm volatile("cp.async.wait_group 1;" ::: "memory");
        else               asm volatile("cp.async.wait_group 0;" ::: "memory");
        __syncthreads();
        if (jt + 2 < jend) stageKV(jt + 2);

        const int buf = jt % 3;
        const uint32_t kbase = smem_base + (buf * AKW) * 2;
        const uint32_t vbase = smem_base + (AV0 + buf * AVW) * 2;

        // --- S = Q @ K^T -----------------------------------------------
        float sacc[8][4];
#pragma unroll
        for (int nt = 0; nt < 8; nt++)
#pragma unroll
            for (int r = 0; r < 4; r++) sacc[nt][r] = 0.0f;
#pragma unroll
        for (int kc = 0; kc < 12; kc++) {
            const int bcol = kc * 16 + ((grp & 1) << 3);
            uint32_t bf[8][2];
#pragma unroll
            for (int ip = 0; ip < 4; ip++) {
                int row = (ip * 2 + (grp >> 1)) * 8 + l7;
                uint32_t addr = kbase + (uint32_t)(row * AKP + bcol) * 2;
                ldmatrix_x4(bf[ip * 2][0], bf[ip * 2][1],
                            bf[ip * 2 + 1][0], bf[ip * 2 + 1][1], addr);
            }
#pragma unroll
            for (int nt = 0; nt < 8; nt++)
                mma_fp16(sacc[nt], qf[kc], bf[nt]);
        }

        // --- mask + online softmax (log2 domain, half2 exp) -------------
        const bool masked = (jt >= 2 * it);
        float mx0 = -INFINITY, mx1 = -INFINITY;
#pragma unroll
        for (int nt = 0; nt < 8; nt++) {
            if (masked) {
                int c0 = jt * 64 + nt * 8 + 2 * t;
                int c1 = c0 + 1;
                if (c0 > r0) sacc[nt][0] = -INFINITY;
                if (c1 > r0) sacc[nt][1] = -INFINITY;
                if (c0 > r1) sacc[nt][2] = -INFINITY;
                if (c1 > r1) sacc[nt][3] = -INFINITY;
            }
            mx0 = fmaxf(mx0, fmaxf(sacc[nt][0], sacc[nt][1]));
            mx1 = fmaxf(mx1, fmaxf(sacc[nt][2], sacc[nt][3]));
        }
        mx0 = fmaxf(mx0, __shfl_xor_sync(0xffffffffu, mx0, 1));
        mx0 = fmaxf(mx0, __shfl_xor_sync(0xffffffffu, mx0, 2));
        mx1 = fmaxf(mx1, __shfl_xor_sync(0xffffffffu, mx1, 1));
        mx1 = fmaxf(mx1, __shfl_xor_sync(0xffffffffu, mx1, 2));

        float mn0 = fmaxf(m0, mx0), mn1 = fmaxf(m1, mx1);
        float corr0 = exp2f(m0 - mn0), corr1 = exp2f(m1 - mn1);
        m0 = mn0; m1 = mn1;
        float ps0 = 0.0f, ps1 = 0.0f;
        uint32_t pf[8][2];
#pragma unroll
        for (int nt = 0; nt < 8; nt++) {
            __half2 pa = h2exp2(__floats2half2_rn(sacc[nt][0] - mn0,
                                                  sacc[nt][1] - mn0));
            __half2 pb = h2exp2(__floats2half2_rn(sacc[nt][2] - mn1,
                                                  sacc[nt][3] - mn1));
            pf[nt][0] = h2u(pa);
            pf[nt][1] = h2u(pb);
            float2 fa = __half22float2(pa), fb = __half22float2(pb);
            ps0 += fa.x + fa.y;
            ps1 += fb.x + fb.y;
        }
        ps0 += __shfl_xor_sync(0xffffffffu, ps0, 1);
        ps0 += __shfl_xor_sync(0xffffffffu, ps0, 2);
        ps1 += __shfl_xor_sync(0xffffffffu, ps1, 1);
        ps1 += __shfl_xor_sync(0xffffffffu, ps1, 2);
        l0 = l0 * corr0 + ps0;
        l1 = l1 * corr1 + ps1;
#pragma unroll
        for (int nt = 0; nt < 16; nt++) {
            oacc[nt][0] *= corr0; oacc[nt][1] *= corr0;
            oacc[nt][2] *= corr1; oacc[nt][3] *= corr1;
        }

        // --- O += P @ V ------------------------------------------------
#pragma unroll
        for (int kc = 0; kc < 4; kc++) {
            uint32_t af[4] = { pf[2 * kc][0], pf[2 * kc][1],
                               pf[2 * kc + 1][0], pf[2 * kc + 1][1] };
            int vrow = kc * 16 + (lane & 15);
            int vhi  = (lane >> 4) & 1;
#pragma unroll
            for (int np = 0; np < 8; np++) {
                uint32_t addr = vbase + (uint32_t)(vrow * AVP + np * 16 + vhi * 8) * 2;
                uint32_t b0, b1, b2, b3;
                ldmatrix_x4_trans(b0, b1, b2, b3, addr);
                uint32_t bb0[2] = { b0, b1 }, bb1[2] = { b2, b3 };
                mma_fp16(oacc[np * 2],     af, bb0);
                mma_fp16(oacc[np * 2 + 1], af, bb1);
            }
        }
    }

    float il0 = 1.0f / l0, il1 = 1.0f / l1;
#pragma unroll
    for (int nt = 0; nt < 16; nt++) {
        int col = nt * 8 + 2 * t;
        *(uint32_t*)(Oattn + (size_t)(b * S_ + r0) * (NQ_ * DH_) + h * DH_ + col) =
            h2u(__floats2half2_rn(oacc[nt][0] * il0, oacc[nt][1] * il0));
        *(uint32_t*)(Oattn + (size_t)(b * S_ + r1) * (NQ_ * DH_) + h * DH_ + col) =
            h2u(__floats2half2_rn(oacc[nt][2] * il1, oacc[nt][3] * il1));
    }
}

// ---------------------------------------------------------------------------
extern "C" void kernel_launch(void* const* d_in, const int* in_sizes, int n_in,
                              void* d_out, int out_size) {
    const float* x     = (const float*)d_in[0];
    const float* cosc  = (const float*)d_in[1];
    const float* sinc  = (const float*)d_in[2];
    const float* W_DKV = (const float*)d_in[5];
    const float* W_UK  = (const float*)d_in[6];
    const float* W_UV  = (const float*)d_in[7];
    const float* W_DQ  = (const float*)d_in[8];
    const float* W_UQ  = (const float*)d_in[9];
    const float* W_KR  = (const float*)d_in[10];
    const float* W_QR  = (const float*)d_in[11];
    const float* W_O   = (const float*)d_in[12];

    float* out    = (float*)d_out;
    float* c_kv   = out + B_ * S_ * DM;
    float* k_rope = c_kv + B_ * S_ * DKV_;

    __half *xh, *krr, *krh, *ckvh, *kch, *vh, *qch, *qrh, *attnh;
    __half *whx, *whkv, *whuq, *whdqh, *who;
    cudaGetSymbolAddress((void**)&xh,    g_xh);
    cudaGetSymbolAddress((void**)&krr,   g_krr);
    cudaGetSymbolAddress((void**)&krh,   g_krh);
    cudaGetSymbolAddress((void**)&ckvh,  g_ckvh);
    cudaGetSymbolAddress((void**)&kch,   g_kch);
    cudaGetSymbolAddress((void**)&vh,    g_vh);
    cudaGetSymbolAddress((void**)&qch,   g_qch);
    cudaGetSymbolAddress((void**)&qrh,   g_qrh);
    cudaGetSymbolAddress((void**)&attnh, g_attnh);
    cudaGetSymbolAddress((void**)&whx,   g_whx);
    cudaGetSymbolAddress((void**)&whkv,  g_whkv);
    cudaGetSymbolAddress((void**)&whuq,  g_whuq);
    cudaGetSymbolAddress((void**)&whdqh, g_whdqh);
    cudaGetSymbolAddress((void**)&who,   g_who);

    cudaFuncSetAttribute(attn_h_kernel, cudaFuncAttributeMaxDynamicSharedMemorySize,
                         ATTN_SMEM);
    cudaFuncSetAttribute(gemm_h<0>, cudaFuncAttributeMaxDynamicSharedMemorySize,
                         GEMM_SMEM);
    cudaFuncSetAttribute(gemm_h<1>, cudaFuncAttributeMaxDynamicSharedMemorySize,
                         GEMM_SMEM);
    cudaFuncSetAttribute(gemm_h<2>, cudaFuncAttributeMaxDynamicSharedMemorySize,
                         GEMM_SMEM);

    // Handles created once and cached (correctness call precedes the
    // pre-capture memory baseline; capture/replay calls allocate nothing).
    static cudaStream_t s1 = nullptr, s2 = nullptr;
    static cudaEvent_t eFork, eT2, eConv, eXg, eRk, eQc, eKV, eDone;
    if (!s1) {
        cudaStreamCreateWithFlags(&s1, cudaStreamNonBlocking);
        cudaStreamCreateWithFlags(&s2, cudaStreamNonBlocking);
        cudaEventCreateWithFlags(&eFork, cudaEventDisableTiming);
        cudaEventCreateWithFlags(&eT2,   cudaEventDisableTiming);
        cudaEventCreateWithFlags(&eConv, cudaEventDisableTiming);
        cudaEventCreateWithFlags(&eXg,   cudaEventDisableTiming);
        cudaEventCreateWithFlags(&eRk,   cudaEventDisableTiming);
        cudaEventCreateWithFlags(&eQc,   cudaEventDisableTiming);
        cudaEventCreateWithFlags(&eKV,   cudaEventDisableTiming);
        cudaEventCreateWithFlags(&eDone, cudaEventDisableTiming);
    }

    cudaEventRecord(eFork, 0);
    cudaStreamWaitEvent(s1, eFork, 0);
    cudaStreamWaitEvent(s2, eFork, 0);

    const float scale2 = 0.072168783648703220563f * 1.4426950408889634f;
    const float SIG = 512.0f;
    dim3 tb(32, 8);
    const int BIG = 1 << 30;

    // s1: Wq combine chain, then late-consumed transposes
    conv_half_kernel<<<(DM * DQC_ / 8 + 255) / 256, 256, 0, s1>>>(W_DQ, whdqh, DM * DQC_ / 8);
    transpose_h_kernel<<<dim3((NQ_ * DH_) / 32, DQC_ / 32), tb, 0, s1>>>(W_UQ, whuq, DQC_, NQ_ * DH_, scale2 * SIG);
    gemm_h<0><<<dim3(DM / 128, (NQ_ * DH_) / 128), 256, GEMM_SMEM, s1>>>(
        whuq, whdqh, whx + 768 * DM, whx + 768 * DM, whx + 768 * DM, whx + 768 * DM,
        nullptr, BIG, BIG, BIG, DM, DM, DM, DM, NQ_ * DH_, DQC_);
    cudaEventRecord(eQc, s1);
    transpose_h_kernel<<<dim3((NKV_ * DH_) / 32, DKV_ / 32), tb, 0, s1>>>(W_UK, whkv, DKV_, NKV_ * DH_, 1.0f / SIG);
    transpose_h_kernel<<<dim3((NKV_ * DH_) / 32, DKV_ / 32), tb, 0, s1>>>(W_UV, whkv + 512 * DKV_, DKV_, NKV_ * DH_, 1.0f);
    transpose_h_kernel<<<dim3(DM / 32, (NQ_ * DH_) / 32), tb, 0, s1>>>(W_O, who, NQ_ * DH_, DM, 1.0f);
    cudaEventRecord(eT2, s1);

    // s2: x -> half
    conv_half_kernel<<<(BS_ * DM / 8 + 255) / 256, 256, 0, s2>>>(x, xh, BS_ * DM / 8);
    cudaEventRecord(eConv, s2);

    // main: whx transposes (dkv, kr, qr), then fused x-GEMM (N=3840)
    transpose_h_kernel<<<dim3(DKV_ / 32, DM / 32), tb>>>(W_DKV, whx, DM, DKV_, 1.0f);
    transpose_h_kernel<<<dim3((NKV_ * DR_) / 32, DM / 32), tb>>>(W_KR, whx + 512 * DM, DM, NKV_ * DR_, 1.0f);
    transpose_h_kernel<<<dim3((NQ_ * DR_) / 32, DM / 32), tb>>>(W_QR, whx + 2816 * DM, DM, NQ_ * DR_, scale2);
    cudaStreamWaitEvent(0, eConv, 0);
    cudaStreamWaitEvent(0, eQc, 0);

    gemm_h<1><<<dim3(3840 / 128, BS_ / 128), 256, GEMM_SMEM>>>(
        xh, whx, ckvh, krr, qch, qrh, c_kv, 512, 768, 2816,
        DKV_, NKV_ * DR_, NQ_ * DH_, NQ_ * DR_, BS_, DM);
    cudaEventRecord(eXg, 0);

    // s1: rope_k (after x-GEMM)
    cudaStreamWaitEvent(s1, eXg, 0);
    rope_k_kernel<<<(BS_ * NKV_ * 32 + 255) / 256, 256, 0, s1>>>(krr, cosc, sinc, k_rope, krh);
    cudaEventRecord(eRk, s1);

    // main: kv-GEMM
    cudaStreamWaitEvent(0, eT2, 0);
    gemm_h<0><<<dim3(1024 / 128, BS_ / 128), 256, GEMM_SMEM>>>(
        ckvh, whkv, kch, vh, vh, vh, nullptr, 512, BIG, BIG,
        NKV_ * DH_, NKV_ * DH_, NKV_ * DH_, NKV_ * DH_, BS_, DKV_);
    cudaEventRecord(eKV, 0);

    // main: attention b=0, then W_O rows [0,2048)
    cudaStreamWaitEvent(0, eRk, 0);
    attn_h_kernel<<<dim3(S_ / 128, NQ_), 256, ATTN_SMEM>>>(
        qch, qrh, kch, krh, vh, cosc, sinc, attnh, 0);
    gemm_h<2><<<dim3(DM / 128, 2048 / 128), 256, GEMM_SMEM>>>(
        attnh, who, out, out, out, out, nullptr, BIG, BIG, BIG,
        DM, DM, DM, DM, 2048, NQ_ * DH_);

    // s2: attention b=1, then W_O rows [2048,4096)  (fills attn0/W_O0 tails)
    cudaStreamWaitEvent(s2, eKV, 0);
    cudaStreamWaitEvent(s2, eRk, 0);
    attn_h_kernel<<<dim3(S_ / 128, NQ_), 256, ATTN_SMEM, s2>>>(
        qch, qrh, kch, krh, vh, cosc, sinc, attnh, 16);
    gemm_h<2><<<dim3(DM / 128, 2048 / 128), 256, GEMM_SMEM, s2>>>(
        attnh + (size_t)2048 * DM, who,
        out + (size_t)2048 * DM, out, out, out, nullptr, BIG, BIG, BIG,
        DM, DM, DM, DM, 2048, NQ_ * DH_);
    cudaEventRecord(eDone, s2);

    // join s2 back into the origin stream (required to end capture cleanly)
    cudaStreamWaitEvent(0, eDone, 0);
}

// round 16
// speedup vs baseline: 1.1082x; 1.0007x over previous
#include <cuda_runtime.h>
#include <cuda_fp16.h>
#include <math.h>
#include <stdint.h>

// Problem constants
#define B_      2
#define S_      2048
#define DM      2048
#define NQ_     16
#define NKV_    4
#define DH_     128
#define DR_     64
#define DKV_    512
#define DQC_    1536
#define BS_     (B_ * S_)        // 4096

// ---------------------------------------------------------------------------
// Scratch (device globals)
// ---------------------------------------------------------------------------
__device__ __align__(256) __half g_xh  [BS_ * DM];
__device__ __align__(256) __half g_krr [BS_ * (NKV_ * DR_)];
__device__ __align__(256) __half g_krh [BS_ * (NKV_ * DR_)];
__device__ __align__(256) __half g_ckvh[BS_ * DKV_];
__device__ __align__(256) __half g_kch [BS_ * (NKV_ * DH_)];
__device__ __align__(256) __half g_vh  [BS_ * (NKV_ * DH_)];
__device__ __align__(256) __half g_qch [BS_ * (NQ_ * DH_)];
__device__ __align__(256) __half g_qrh [BS_ * (NQ_ * DR_)];
__device__ __align__(256) __half g_attnh[BS_ * (NQ_ * DH_)];

// whx rows: [0,512) dkv | [512,768) kr | [768,2816) Wq | [2816,3840) qr
__device__ __align__(256) __half g_whx [3840 * DM];
__device__ __align__(256) __half g_whkv[1024 * DKV_];          // uk(/SIG) | uv
__device__ __align__(256) __half g_whuq[(NQ_ * DH_) * DQC_];
__device__ __align__(256) __half g_whdqh[DM * DQC_];
__device__ __align__(256) __half g_who [DM * (NQ_ * DH_)];

// ---------------------------------------------------------------------------
__device__ __forceinline__ uint32_t h2u(__half2 h) { return *(uint32_t*)&h; }

__device__ __forceinline__ void mma_fp16(float* d, const uint32_t* a,
                                         const uint32_t* b) {
    asm volatile(
        "mma.sync.aligned.m16n8k16.row.col.f32.f16.f16.f32 "
        "{%0,%1,%2,%3}, {%4,%5,%6,%7}, {%8,%9}, {%0,%1,%2,%3};"
        : "+f"(d[0]), "+f"(d[1]), "+f"(d[2]), "+f"(d[3])
        : "r"(a[0]), "r"(a[1]), "r"(a[2]), "r"(a[3]), "r"(b[0]), "r"(b[1]));
}

__device__ __forceinline__ void cp_async16(uint32_t saddr, const void* gptr) {
    asm volatile("cp.async.cg.shared.global [%0], [%1], 16;"
                 :: "r"(saddr), "l"(gptr));
}
#define CP_COMMIT() asm volatile("cp.async.commit_group;" ::: "memory")

__device__ __forceinline__ void ldmatrix_x4(uint32_t& d0, uint32_t& d1,
                                            uint32_t& d2, uint32_t& d3,
                                            uint32_t addr) {
    asm volatile("ldmatrix.sync.aligned.m8n8.x4.shared.b16 "
                 "{%0,%1,%2,%3}, [%4];"
                 : "=r"(d0), "=r"(d1), "=r"(d2), "=r"(d3) : "r"(addr));
}
__device__ __forceinline__ void ldmatrix_x4_trans(uint32_t& d0, uint32_t& d1,
                                                  uint32_t& d2, uint32_t& d3,
                                                  uint32_t addr) {
    asm volatile("ldmatrix.sync.aligned.m8n8.x4.trans.shared.b16 "
                 "{%0,%1,%2,%3}, [%4];"
                 : "=r"(d0), "=r"(d1), "=r"(d2), "=r"(d3) : "r"(addr));
}

extern __shared__ uint32_t dyn_smem_u32[];

// ---------------------------------------------------------------------------
__global__ __launch_bounds__(256)
void conv_half_kernel(const float* __restrict__ in, __half* __restrict__ out,
                      int n8) {
    int idx = blockIdx.x * blockDim.x + threadIdx.x;
    if (idx >= n8) return;
    float4 a = ((const float4*)in)[idx * 2];
    float4 b = ((const float4*)in)[idx * 2 + 1];
    uint4 o = { h2u(__floats2half2_rn(a.x, a.y)), h2u(__floats2half2_rn(a.z, a.w)),
                h2u(__floats2half2_rn(b.x, b.y)), h2u(__floats2half2_rn(b.z, b.w)) };
    ((uint4*)out)[idx] = o;
}

__global__ __launch_bounds__(256)
void transpose_h_kernel(const float* __restrict__ in, __half* __restrict__ out,
                        int K, int N, float mul) {
    __shared__ float t[32][33];
    int bx = blockIdx.x * 32;
    int by = blockIdx.y * 32;
    int x = bx + threadIdx.x;
#pragma unroll
    for (int i = threadIdx.y; i < 32; i += 8)
        t[i][threadIdx.x] = in[(size_t)(by + i) * N + x];
    __syncthreads();
    int xo = by + threadIdx.x;
#pragma unroll
    for (int i = threadIdx.y; i < 32; i += 8)
        out[(size_t)(bx + i) * K + xo] = __float2half(t[threadIdx.x][i] * mul);
}

// ---------------------------------------------------------------------------
// fp16 mma.sync GEMM, cp.async 3-stage ring, one barrier per K-tile,
// ldmatrix frags, multi-destination epilogue.
// ---------------------------------------------------------------------------
#define GLDH 36
#define GTILE (128 * GLDH)
#define GNST 3
#define GEMM_SMEM (GNST * 2 * GTILE * 4)

template <int OM>
__global__ __launch_bounds__(256, 1)
void gemm_h(const __half* __restrict__ A, const __half* __restrict__ BT,
            void* d0v, void* d1v, void* d2v, void* d3v, float* mirror,
            int s1, int s2, int s3,
            int l0, int l1, int l2, int l3,
            int M, int K) {
    const uint32_t smem_base = (uint32_t)__cvta_generic_to_shared(dyn_smem_u32);
    const int tid = threadIdx.x;
    const int wid = tid >> 5, lane = tid & 31;
    const int g = lane >> 2, t = lane & 3;
    const int m0 = blockIdx.y * 128, n0 = blockIdx.x * 128;
    const int wm = (wid >> 2) * 64, wn = (wid & 3) * 32;
    const int grp = lane >> 3;
    const int l7 = lane & 7;

    float cf[4][4][4];
#pragma unroll
    for (int i = 0; i < 4; i++)
#pragma unroll
        for (int j = 0; j < 4; j++)
#pragma unroll
            for (int r = 0; r < 4; r++) cf[i][j][r] = 0.0f;

    const int T = K >> 6;

    auto stage = [&](int kt) {
        const int buf = kt % GNST;
        const int k0 = kt << 6;
        uint32_t aS = smem_base + buf * (2 * GTILE * 4);
        uint32_t bS = aS + GTILE * 4;
#pragma unroll
        for (int i = 0; i < 4; i++) {
            int idx = tid + (i << 8);
            int r = idx >> 3, c = idx & 7;
            uint32_t so = (uint32_t)(r * GLDH + c * 4) * 4;
            cp_async16(aS + so, A + (size_t)(m0 + r) * K + k0 + c * 8);
            cp_async16(bS + so, BT + (size_t)(n0 + r) * K + k0 + c * 8);
        }
        CP_COMMIT();
    };

    stage(0);
    stage(1);

    for (int kt = 0; kt < T; kt++) {
        if (kt + 1 < T) asm volatile("cp.async.wait_group 1;" ::: "memory");
        else            asm volatile("cp.async.wait_group 0;" ::: "memory");
        __syncthreads();
        if (kt + 2 < T) stage(kt + 2);

        const int buf = kt % GNST;
        const uint32_t aSa = smem_base + buf * (2 * GTILE * 4);
        const uint32_t bSa = aSa + GTILE * 4;
#pragma unroll
        for (int kc = 0; kc < 4; kc++) {
            const int acol = kc * 16 + ((grp >> 1) << 3);
            const int arow = ((grp & 1) << 3) + l7;
            uint32_t af[4][4], bf[4][2];
#pragma unroll
            for (int im = 0; im < 4; im++) {
                uint32_t addr = aSa + (uint32_t)((wm + im * 16 + arow) * 72 + acol) * 2;
                ldmatrix_x4(af[im][0], af[im][1], af[im][2], af[im][3], addr);
            }
            const int bcol = kc * 16 + ((grp & 1) << 3);
#pragma unroll
            for (int ip = 0; ip < 2; ip++) {
                int row = wn + (ip * 2 + (grp >> 1)) * 8 + l7;
                uint32_t addr = bSa + (uint32_t)(row * 72 + bcol) * 2;
                ldmatrix_x4(bf[ip * 2][0], bf[ip * 2][1],
                            bf[ip * 2 + 1][0], bf[ip * 2 + 1][1], addr);
            }
#pragma unroll
            for (int im = 0; im < 4; im++)
#pragma unroll
                for (int in_ = 0; in_ < 4; in_++)
                    mma_fp16(cf[im][in_], af[im], bf[in_]);
        }
    }

    void* dstv; int ld, cb, seg;
    if (n0 < s1)      { dstv = d0v; ld = l0; cb = n0;      seg = 0; }
    else if (n0 < s2) { dstv = d1v; ld = l1; cb = n0 - s1; seg = 1; }
    else if (n0 < s3) { dstv = d2v; ld = l2; cb = n0 - s2; seg = 2; }
    else              { dstv = d3v; ld = l3; cb = n0 - s3; seg = 3; }

#pragma unroll
    for (int im = 0; im < 4; im++) {
#pragma unroll
        for (int in_ = 0; in_ < 4; in_++) {
            int row = m0 + wm + im * 16 + g;
            int col = cb + wn + in_ * 8 + 2 * t;
            if (OM == 2) {
                float* dst = (float*)dstv;
                *(float2*)(dst + (size_t)row * ld + col) =
                    make_float2(cf[im][in_][0], cf[im][in_][1]);
                *(float2*)(dst + (size_t)(row + 8) * ld + col) =
                    make_float2(cf[im][in_][2], cf[im][in_][3]);
            } else {
                __half* dst = (__half*)dstv;
                *(uint32_t*)(dst + (size_t)row * ld + col) =
                    h2u(__floats2half2_rn(cf[im][in_][0], cf[im][in_][1]));
                *(uint32_t*)(dst + (size_t)(row + 8) * ld + col) =
                    h2u(__floats2half2_rn(cf[im][in_][2], cf[im][in_][3]));
                if (OM == 1 && seg == 0) {
                    *(float2*)(mirror + (size_t)row * ld + col) =
                        make_float2(cf[im][in_][0], cf[im][in_][1]);
                    *(float2*)(mirror + (size_t)(row + 8) * ld + col) =
                        make_float2(cf[im][in_][2], cf[im][in_][3]);
                }
            }
        }
    }
}

// ---------------------------------------------------------------------------
// RoPE for K, one batch per launch (fp32 output + half copy)
// ---------------------------------------------------------------------------
__global__ __launch_bounds__(256)
void rope_k_kernel(const __half* __restrict__ kr_raw,
                   const float* __restrict__ cosc, const float* __restrict__ sinc,
                   float* __restrict__ kr_out, __half* __restrict__ kr_h,
                   int b) {
    int idx = blockIdx.x * blockDim.x + threadIdx.x;
    if (idx >= S_ * NKV_ * 32) return;
    int d  = idx & 31;
    int kv = (idx >> 5) & 3;
    int s  = idx >> 7;                      // [0, 2048)
    int in_base = (b * S_ + s) * (NKV_ * DR_) + kv * DR_;
    float x1 = __half2float(kr_raw[in_base + d]);
    float x2 = __half2float(kr_raw[in_base + d + 32]);
    float c = cosc[s * DR_ + d];
    float sn = sinc[s * DR_ + d];
    float y1 = x1 * c - x2 * sn;
    float y2 = x2 * c + x1 * sn;
    int ob = ((b * NKV_ + kv) * S_ + s) * DR_;
    kr_out[ob + d]      = y1;
    kr_out[ob + d + 32] = y2;
    kr_h[ob + d]        = __float2half(y1);
    kr_h[ob + d + 32]   = __float2half(y2);
}

// ---------------------------------------------------------------------------
// fp16 flash attention: 3-buffer K/V ring, one barrier/tile, register P,
// h2exp2 softmax. bh_base selects the batch half.
// ---------------------------------------------------------------------------
#define AKP 200
#define AVP 136
#define AKW (64 * AKP)
#define AVW (64 * AVP)
#define AV0 (3 * AKW)
#define ATTN_SMEM ((AV0 + 3 * AVW) * 2)    // 129024 B

__global__ __launch_bounds__(256, 1)
void attn_h_kernel(const __half* __restrict__ Qc, const __half* __restrict__ Qr,
                   const __half* __restrict__ Kc, const __half* __restrict__ Kr,
                   const __half* __restrict__ V,
                   const float* __restrict__ cosc, const float* __restrict__ sinc,
                   __half* __restrict__ Oattn, int bh_base) {
    __half* smh = (__half*)dyn_smem_u32;
    const uint32_t smem_base = (uint32_t)__cvta_generic_to_shared(smh);

    const int tid = threadIdx.x;
    const int w = tid >> 5, lane = tid & 31;
    const int g = lane >> 2, t = lane & 3;
    const int grp = lane >> 3;
    const int l7 = lane & 7;
    const int it = (gridDim.x - 1) - blockIdx.x;
    const int bh = blockIdx.y + bh_base;
    const int b = bh >> 4, h = bh & 15;
    const int kvh = h >> 2;

    const int r0 = it * 128 + w * 16 + g;
    const int r1 = r0 + 8;

    const int srow = tid >> 2, sc = tid & 3;
    auto stageKV = [&](int jt) {
        const int buf = jt % 3;
        const int kg = jt * 64 + srow;
        const __half* kcrow = Kc + (size_t)(b * S_ + kg) * (NKV_ * DH_) + kvh * DH_;
        const __half* krrow = Kr + ((size_t)(b * NKV_ + kvh) * S_ + kg) * DR_;
        const __half* vrow  = V  + (size_t)(b * S_ + kg) * (NKV_ * DH_) + kvh * DH_;
        uint32_t kS = smem_base + (buf * AKW + srow * AKP) * 2;
        uint32_t vS = smem_base + (AV0 + buf * AVW + srow * AVP) * 2;
#pragma unroll
        for (int j = 0; j < 6; j++) {
            int c = sc + j * 4;
            const __half* src = (c < 16) ? (kcrow + c * 8) : (krrow + (c - 16) * 8);
            cp_async16(kS + c * 16, src);
        }
#pragma unroll
        for (int j = 0; j < 4; j++) {
            int c = sc + j * 4;
            cp_async16(vS + c * 16, vrow + c * 8);
        }
        CP_COMMIT();
    };

    // Prefetch the first two K/V tiles BEFORE the Q-fragment load, so the
    // cp.async traffic overlaps the Q global-load dependency chain.
    stageKV(0);
    stageKV(1);

    // Q fragments
    uint32_t qf[12][4];
    {
        const __half* qc0 = Qc + (size_t)(b * S_ + r0) * (NQ_ * DH_) + h * DH_;
        const __half* qc1 = Qc + (size_t)(b * S_ + r1) * (NQ_ * DH_) + h * DH_;
#pragma unroll
        for (int kc = 0; kc < 8; kc++) {
            int c = kc * 16 + 2 * t;
            qf[kc][0] = *(const uint32_t*)(qc0 + c);
            qf[kc][1] = *(const uint32_t*)(qc1 + c);
            qf[kc][2] = *(const uint32_t*)(qc0 + c + 8);
            qf[kc][3] = *(const uint32_t*)(qc1 + c + 8);
        }
        const __half* qr0 = Qr + (size_t)(b * S_ + r0) * (NQ_ * DR_) + h * DR_;
        const __half* qr1 = Qr + (size_t)(b * S_ + r1) * (NQ_ * DR_) + h * DR_;
#pragma unroll
        for (int p = 0; p < 2; p++) {
            int cA = p * 16 + 2 * t;
#pragma unroll
            for (int jj = 0; jj < 4; jj++) {
                const __half* qp = (jj & 1) ? qr1 : qr0;
                int s = (jj & 1) ? r1 : r0;
                int c = cA + (jj >> 1) * 8;
                float2 xA = __half22float2(*(const __half2*)(qp + c));
                float2 xB = __half22float2(*(const __half2*)(qp + c + 32));
                float2 cs = *(const float2*)(cosc + s * DR_ + c);
                float2 sn = *(const float2*)(sinc + s * DR_ + c);
                qf[8 + p][jj]  = h2u(__floats2half2_rn(
                    xA.x * cs.x - xB.x * sn.x, xA.y * cs.y - xB.y * sn.y));
                qf[10 + p][jj] = h2u(__floats2half2_rn(
                    xB.x * cs.x + xA.x * sn.x, xB.y * cs.y + xA.y * sn.y));
            }
        }
    }

    float oacc[16][4];
#pragma unroll
    for (int nt = 0; nt < 16; nt++)
#pragma unroll
        for (int r = 0; r < 4; r++) oacc[nt][r] = 0.0f;
    float m0 = -INFINITY, m1 = -INFINITY, l0 = 0.0f, l1 = 0.0f;

    const int jend = 2 * it + 2;

    for (int jt = 0; jt < jend; jt++) {
        if (jt + 1 < jend) asm volatile("cp.async.wait_group 1;" ::: "memory");
        else               asm volatile("cp.async.wait_group 0;" ::: "memory");
        __syncthreads();
        if (jt + 2 < jend) stageKV(jt + 2);

        const int buf = jt % 3;
        const uint32_t kbase = smem_base + (buf * AKW) * 2;
        const uint32_t vbase = smem_base + (AV0 + buf * AVW) * 2;

        // --- S = Q @ K^T -----------------------------------------------
        float sacc[8][4];
#pragma unroll
        for (int nt = 0; nt < 8; nt++)
#pragma unroll
            for (int r = 0; r < 4; r++) sacc[nt][r] = 0.0f;
#pragma unroll
        for (int kc = 0; kc < 12; kc++) {
            const int bcol = kc * 16 + ((grp & 1) << 3);
            uint32_t bf[8][2];
#pragma unroll
            for (int ip = 0; ip < 4; ip++) {
                int row = (ip * 2 + (grp >> 1)) * 8 + l7;
                uint32_t addr = kbase + (uint32_t)(row * AKP + bcol) * 2;
                ldmatrix_x4(bf[ip * 2][0], bf[ip * 2][1],
                            bf[ip * 2 + 1][0], bf[ip * 2 + 1][1], addr);
            }
#pragma unroll
            for (int nt = 0; nt < 8; nt++)
                mma_fp16(sacc[nt], qf[kc], bf[nt]);
        }

        // --- mask + online softmax (log2 domain, half2 exp) -------------
        const bool masked = (jt >= 2 * it);
        float mx0 = -INFINITY, mx1 = -INFINITY;
#pragma unroll
        for (int nt = 0; nt < 8; nt++) {
            if (masked) {
                int c0 = jt * 64 + nt * 8 + 2 * t;
                int c1 = c0 + 1;
                if (c0 > r0) sacc[nt][0] = -INFINITY;
                if (c1 > r0) sacc[nt][1] = -INFINITY;
                if (c0 > r1) sacc[nt][2] = -INFINITY;
                if (c1 > r1) sacc[nt][3] = -INFINITY;
            }
            mx0 = fmaxf(mx0, fmaxf(sacc[nt][0], sacc[nt][1]));
            mx1 = fmaxf(mx1, fmaxf(sacc[nt][2], sacc[nt][3]));
        }
        mx0 = fmaxf(mx0, __shfl_xor_sync(0xffffffffu, mx0, 1));
        mx0 = fmaxf(mx0, __shfl_xor_sync(0xffffffffu, mx0, 2));
        mx1 = fmaxf(mx1, __shfl_xor_sync(0xffffffffu, mx1, 1));
        mx1 = fmaxf(mx1, __shfl_xor_sync(0xffffffffu, mx1, 2));

        float mn0 = fmaxf(m0, mx0), mn1 = fmaxf(m1, mx1);
        float corr0 = exp2f(m0 - mn0), corr1 = exp2f(m1 - mn1);
        m0 = mn0; m1 = mn1;
        float ps0 = 0.0f, ps1 = 0.0f;
        uint32_t pf[8][2];
#pragma unroll
        for (int nt = 0; nt < 8; nt++) {
            __half2 pa = h2exp2(__floats2half2_rn(sacc[nt][0] - mn0,
                                                  sacc[nt][1] - mn0));
            __half2 pb = h2exp2(__floats2half2_rn(sacc[nt][2] - mn1,
                                                  sacc[nt][3] - mn1));
            pf[nt][0] = h2u(pa);
            pf[nt][1] = h2u(pb);
            float2 fa = __half22float2(pa), fb = __half22float2(pb);
            ps0 += fa.x + fa.y;
            ps1 += fb.x + fb.y;
        }
        ps0 += __shfl_xor_sync(0xffffffffu, ps0, 1);
        ps0 += __shfl_xor_sync(0xffffffffu, ps0, 2);
        ps1 += __shfl_xor_sync(0xffffffffu, ps1, 1);
        ps1 += __shfl_xor_sync(0xffffffffu, ps1, 2);
        l0 = l0 * corr0 + ps0;
        l1 = l1 * corr1 + ps1;
#pragma unroll
        for (int nt = 0; nt < 16; nt++) {
            oacc[nt][0] *= corr0; oacc[nt][1] *= corr0;
            oacc[nt][2] *= corr1; oacc[nt][3] *= corr1;
        }

        // --- O += P @ V ------------------------------------------------
#pragma unroll
        for (int kc = 0; kc < 4; kc++) {
            uint32_t af[4] = { pf[2 * kc][0], pf[2 * kc][1],
                               pf[2 * kc + 1][0], pf[2 * kc + 1][1] };
            int vrow = kc * 16 + (lane & 15);
            int vhi  = (lane >> 4) & 1;
#pragma unroll
            for (int np = 0; np < 8; np++) {
                uint32_t addr = vbase + (uint32_t)(vrow * AVP + np * 16 + vhi * 8) * 2;
                uint32_t b0, b1, b2, b3;
                ldmatrix_x4_trans(b0, b1, b2, b3, addr);
                uint32_t bb0[2] = { b0, b1 }, bb1[2] = { b2, b3 };
                mma_fp16(oacc[np * 2],     af, bb0);
                mma_fp16(oacc[np * 2 + 1], af, bb1);
            }
        }
    }

    float il0 = 1.0f / l0, il1 = 1.0f / l1;
#pragma unroll
    for (int nt = 0; nt < 16; nt++) {
        int col = nt * 8 + 2 * t;
        *(uint32_t*)(Oattn + (size_t)(b * S_ + r0) * (NQ_ * DH_) + h * DH_ + col) =
            h2u(__floats2half2_rn(oacc[nt][0] * il0, oacc[nt][1] * il0));
        *(uint32_t*)(Oattn + (size_t)(b * S_ + r1) * (NQ_ * DH_) + h * DH_ + col) =
            h2u(__floats2half2_rn(oacc[nt][2] * il1, oacc[nt][3] * il1));
    }
}

// ---------------------------------------------------------------------------
extern "C" void kernel_launch(void* const* d_in, const int* in_sizes, int n_in,
                              void* d_out, int out_size) {
    const float* x     = (const float*)d_in[0];
    const float* cosc  = (const float*)d_in[1];
    const float* sinc  = (const float*)d_in[2];
    const float* W_DKV = (const float*)d_in[5];
    const float* W_UK  = (const float*)d_in[6];
    const float* W_UV  = (const float*)d_in[7];
    const float* W_DQ  = (const float*)d_in[8];
    const float* W_UQ  = (const float*)d_in[9];
    const float* W_KR  = (const float*)d_in[10];
    const float* W_QR  = (const float*)d_in[11];
    const float* W_O   = (const float*)d_in[12];

    float* out    = (float*)d_out;
    float* c_kv   = out + B_ * S_ * DM;
    float* k_rope = c_kv + B_ * S_ * DKV_;

    __half *xh, *krr, *krh, *ckvh, *kch, *vh, *qch, *qrh, *attnh;
    __half *whx, *whkv, *whuq, *whdqh, *who;
    cudaGetSymbolAddress((void**)&xh,    g_xh);
    cudaGetSymbolAddress((void**)&krr,   g_krr);
    cudaGetSymbolAddress((void**)&krh,   g_krh);
    cudaGetSymbolAddress((void**)&ckvh,  g_ckvh);
    cudaGetSymbolAddress((void**)&kch,   g_kch);
    cudaGetSymbolAddress((void**)&vh,    g_vh);
    cudaGetSymbolAddress((void**)&qch,   g_qch);
    cudaGetSymbolAddress((void**)&qrh,   g_qrh);
    cudaGetSymbolAddress((void**)&attnh, g_attnh);
    cudaGetSymbolAddress((void**)&whx,   g_whx);
    cudaGetSymbolAddress((void**)&whkv,  g_whkv);
    cudaGetSymbolAddress((void**)&whuq,  g_whuq);
    cudaGetSymbolAddress((void**)&whdqh, g_whdqh);
    cudaGetSymbolAddress((void**)&who,   g_who);

    cudaFuncSetAttribute(attn_h_kernel, cudaFuncAttributeMaxDynamicSharedMemorySize,
                         ATTN_SMEM);
    cudaFuncSetAttribute(gemm_h<0>, cudaFuncAttributeMaxDynamicSharedMemorySize,
                         GEMM_SMEM);
    cudaFuncSetAttribute(gemm_h<1>, cudaFuncAttributeMaxDynamicSharedMemorySize,
                         GEMM_SMEM);
    cudaFuncSetAttribute(gemm_h<2>, cudaFuncAttributeMaxDynamicSharedMemorySize,
                         GEMM_SMEM);

    // Handles created once and cached (correctness call precedes the
    // pre-capture memory baseline; capture/replay calls allocate nothing).
    static cudaStream_t s1 = nullptr, s2 = nullptr;
    static cudaEvent_t eFork, eT2, eConv, eXg, eQc, eB1, eDone;
    if (!s1) {
        cudaStreamCreateWithFlags(&s1, cudaStreamNonBlocking);
        cudaStreamCreateWithFlags(&s2, cudaStreamNonBlocking);
        cudaEventCreateWithFlags(&eFork, cudaEventDisableTiming);
        cudaEventCreateWithFlags(&eT2,   cudaEventDisableTiming);
        cudaEventCreateWithFlags(&eConv, cudaEventDisableTiming);
        cudaEventCreateWithFlags(&eXg,   cudaEventDisableTiming);
        cudaEventCreateWithFlags(&eQc,   cudaEventDisableTiming);
        cudaEventCreateWithFlags(&eB1,   cudaEventDisableTiming);
        cudaEventCreateWithFlags(&eDone, cudaEventDisableTiming);
    }

    cudaEventRecord(eFork, 0);
    cudaStreamWaitEvent(s1, eFork, 0);
    cudaStreamWaitEvent(s2, eFork, 0);

    const float scale2 = 0.072168783648703220563f * 1.4426950408889634f;
    const float SIG = 512.0f;
    dim3 tb(32, 8);
    const int BIG = 1 << 30;

    // s1: Wq combine chain, then late-consumed transposes
    conv_half_kernel<<<(DM * DQC_ / 8 + 255) / 256, 256, 0, s1>>>(W_DQ, whdqh, DM * DQC_ / 8);
    transpose_h_kernel<<<dim3((NQ_ * DH_) / 32, DQC_ / 32), tb, 0, s1>>>(W_UQ, whuq, DQC_, NQ_ * DH_, scale2 * SIG);
    gemm_h<0><<<dim3(DM / 128, (NQ_ * DH_) / 128), 256, GEMM_SMEM, s1>>>(
        whuq, whdqh, whx + 768 * DM, whx + 768 * DM, whx + 768 * DM, whx + 768 * DM,
        nullptr, BIG, BIG, BIG, DM, DM, DM, DM, NQ_ * DH_, DQC_);
    cudaEventRecord(eQc, s1);
    transpose_h_kernel<<<dim3((NKV_ * DH_) / 32, DKV_ / 32), tb, 0, s1>>>(W_UK, whkv, DKV_, NKV_ * DH_, 1.0f / SIG);
    transpose_h_kernel<<<dim3((NKV_ * DH_) / 32, DKV_ / 32), tb, 0, s1>>>(W_UV, whkv + 512 * DKV_, DKV_, NKV_ * DH_, 1.0f);
    transpose_h_kernel<<<dim3(DM / 32, (NQ_ * DH_) / 32), tb, 0, s1>>>(W_O, who, NQ_ * DH_, DM, 1.0f);
    cudaEventRecord(eT2, s1);

    // s2: x -> half
    conv_half_kernel<<<(BS_ * DM / 8 + 255) / 256, 256, 0, s2>>>(x, xh, BS_ * DM / 8);
    cudaEventRecord(eConv, s2);

    // main: whx transposes (dkv, kr, qr), then fused x-GEMM (N=3840)
    transpose_h_kernel<<<dim3(DKV_ / 32, DM / 32), tb>>>(W_DKV, whx, DM, DKV_, 1.0f);
    transpose_h_kernel<<<dim3((NKV_ * DR_) / 32, DM / 32), tb>>>(W_KR, whx + 512 * DM, DM, NKV_ * DR_, 1.0f);
    transpose_h_kernel<<<dim3((NQ_ * DR_) / 32, DM / 32), tb>>>(W_QR, whx + 2816 * DM, DM, NQ_ * DR_, scale2);
    cudaStreamWaitEvent(0, eConv, 0);
    cudaStreamWaitEvent(0, eQc, 0);

    gemm_h<1><<<dim3(3840 / 128, BS_ / 128), 256, GEMM_SMEM>>>(
        xh, whx, ckvh, krr, qch, qrh, c_kv, 512, 768, 2816,
        DKV_, NKV_ * DR_, NQ_ * DH_, NQ_ * DR_, BS_, DM);
    cudaEventRecord(eXg, 0);

    // main: b=0 chain — rope_k(b0), kv(b0), attn(b0), W_O(rows 0..2047)
    cudaStreamWaitEvent(0, eT2, 0);
    rope_k_kernel<<<(S_ * NKV_ * 32 + 255) / 256, 256>>>(krr, cosc, sinc, k_rope, krh, 0);
    gemm_h<0><<<dim3(1024 / 128, 2048 / 128), 256, GEMM_SMEM>>>(
        ckvh, whkv, kch, vh, vh, vh, nullptr, 512, BIG, BIG,
        NKV_ * DH_, NKV_ * DH_, NKV_ * DH_, NKV_ * DH_, 2048, DKV_);
    attn_h_kernel<<<dim3(S_ / 128, NQ_), 256, ATTN_SMEM>>>(
        qch, qrh, kch, krh, vh, cosc, sinc, attnh, 0);
    gemm_h<2><<<dim3(DM / 128, 2048 / 128), 256, GEMM_SMEM>>>(
        attnh, who, out, out, out, out, nullptr, BIG, BIG, BIG,
        DM, DM, DM, DM, 2048, NQ_ * DH_);

    // s1: b=1 prep — rope_k(b1), kv(b1)  (concurrent with main's b0 prep)
    cudaStreamWaitEvent(s1, eXg, 0);
    rope_k_kernel<<<(S_ * NKV_ * 32 + 255) / 256, 256, 0, s1>>>(krr, cosc, sinc, k_rope, krh, 1);
    gemm_h<0><<<dim3(1024 / 128, 2048 / 128), 256, GEMM_SMEM, s1>>>(
        ckvh + (size_t)2048 * DKV_, whkv,
        kch + (size_t)2048 * (NKV_ * DH_), vh + (size_t)2048 * (NKV_ * DH_),
        vh, vh, nullptr, 512, BIG, BIG,
        NKV_ * DH_, NKV_ * DH_, NKV_ * DH_, NKV_ * DH_, 2048, DKV_);
    cudaEventRecord(eB1, s1);

    // s2: b=1 chain — attn(b1), W_O(rows 2048..4095)  (fills b0 tails)
    cudaStreamWaitEvent(s2, eB1, 0);
    attn_h_kernel<<<dim3(S_ / 128, NQ_), 256, ATTN_SMEM, s2>>>(
        qch, qrh, kch, krh, vh, cosc, sinc, attnh, 16);
    gemm_h<2><<<dim3(DM / 128, 2048 / 128), 256, GEMM_SMEM, s2>>>(
        attnh + (size_t)2048 * DM, who,
        out + (size_t)2048 * DM, out, out, out, nullptr, BIG, BIG, BIG,
        DM, DM, DM, DM, 2048, NQ_ * DH_);
    cudaEventRecord(eDone, s2);

    // join s2 back into the origin stream
    cudaStreamWaitEvent(0, eDone, 0);
}